// round 6
// baseline (speedup 1.0000x reference)
#include <cuda_runtime.h>
#include <math.h>

#define NLEV 16
#define TABLE_SIZE (1u << 19)
#define TMASK (TABLE_SIZE - 1u)
#define PRIME_Y 2654435761u
#define PRIME_Z 805459861u
#define TPB 256

struct InvArr { float v[NLEV]; };   // res/2 per level

// ---- load phase: weights + all gathers for one level -----------------------
// PRIME_X == 1: for even bl.x the corners (bl.x, bl.x+1) hash to h and h^1 ->
// one aligned float4 load. Odd bl.x: two float2 loads per (y,z) combo.
__device__ __forceinline__ void load_level(
    const float* __restrict__ emb, int lvl, float invg,
    float X0, float X1, float X2,
    float4 e[4], unsigned& meta, float& w0, float& w1, float& w2)
{
    const float t0 = X0 * invg, t1 = X1 * invg, t2 = X2 * invg;
    const float f0 = floorf(t0), f1 = floorf(t1), f2 = floorf(t2);
    w0 = t0 - f0; w1 = t1 - f1; w2 = t2 - f2;

    const unsigned hx = (unsigned)(int)f0;
    const unsigned hy = (unsigned)(int)f1 * PRIME_Y;
    const unsigned hz = (unsigned)(int)f2 * PRIME_Z;
    const unsigned r0 = hy ^ hz;
    const unsigned r1 = hy ^ (hz + PRIME_Z);
    const unsigned r2 = (hy + PRIME_Y) ^ hz;
    const unsigned r3 = (hy + PRIME_Y) ^ (hz + PRIME_Z);
    const unsigned h0 = (hx ^ r0) & TMASK, h1 = (hx ^ r1) & TMASK;
    const unsigned h2 = (hx ^ r2) & TMASK, h3 = (hx ^ r3) & TMASK;

    const float2* tab2 = (const float2*)emb + (size_t)lvl * TABLE_SIZE;
    const float4* tab4 = (const float4*)tab2;

    if ((hx & 1u) == 0u) {
        e[0] = __ldg(&tab4[h0 >> 1]);
        e[1] = __ldg(&tab4[h1 >> 1]);
        e[2] = __ldg(&tab4[h2 >> 1]);
        e[3] = __ldg(&tab4[h3 >> 1]);
        // odd h: corner bl lives in .zw, bl+1 in .xy -> swap weights at consume
        meta = (h0 & 1u) | ((h1 & 1u) << 1) | ((h2 & 1u) << 2) | ((h3 & 1u) << 3);
    } else {
        const unsigned hx1 = hx + 1u;
        const unsigned g0 = (hx1 ^ r0) & TMASK, g1 = (hx1 ^ r1) & TMASK;
        const unsigned g2 = (hx1 ^ r2) & TMASK, g3 = (hx1 ^ r3) & TMASK;
        float2 a0 = __ldg(&tab2[h0]), b0 = __ldg(&tab2[g0]);
        float2 a1 = __ldg(&tab2[h1]), b1 = __ldg(&tab2[g1]);
        float2 a2 = __ldg(&tab2[h2]), b2 = __ldg(&tab2[g2]);
        float2 a3 = __ldg(&tab2[h3]), b3 = __ldg(&tab2[g3]);
        e[0] = make_float4(a0.x, a0.y, b0.x, b0.y);
        e[1] = make_float4(a1.x, a1.y, b1.x, b1.y);
        e[2] = make_float4(a2.x, a2.y, b2.x, b2.y);
        e[3] = make_float4(a3.x, a3.y, b3.x, b3.y);
        meta = 0u;
    }
}

// ---- consume: trilinear accumulate (swap WEIGHTS, not values: 2 SEL/corner)
__device__ __forceinline__ void consume_level(
    const float4 e[4], unsigned meta,
    float w0, float w1, float w2, float& a0, float& a1)
{
    const float u0 = 1.f - w0, u1 = 1.f - w1, u2 = 1.f - w2;
    float c[4];
    c[0] = u1 * u2; c[1] = u1 * w2; c[2] = w1 * u2; c[3] = w1 * w2;
    a0 = 0.f; a1 = 0.f;
#pragma unroll
    for (int k = 0; k < 4; ++k) {
        const bool sw = (meta >> k) & 1u;
        const float wA = c[k] * (sw ? w0 : u0);   // weight for slots .xy
        const float wB = c[k] * (sw ? u0 : w0);   // weight for slots .zw
        a0 = fmaf(wA, e[k].x, fmaf(wB, e[k].z, a0));
        a1 = fmaf(wA, e[k].y, fmaf(wB, e[k].w, a1));
    }
}

__global__ void __launch_bounds__(TPB, 4)
ingp_hash_kernel(const float* __restrict__ x,
                 const float* __restrict__ emb,
                 float* __restrict__ out,
                 int n, InvArr inv)
{
    // pitch-33 rows: conflict-free staged writes AND coalesced readback
    __shared__ float stage[TPB * 33];

    const int tid = threadIdx.x;
    const int stride = gridDim.x * TPB;

    // persistent grid-stride: keeps every SM at full residency (no wave tail)
    for (int base_pt = blockIdx.x * TPB; base_pt < n; base_pt += stride) {
        const int pid = base_pt + tid;

        float x0 = 0.f, x1 = 0.f, x2 = 0.f;
        if (pid < n) {
            x0 = x[3 * pid + 0];
            x1 = x[3 * pid + 1];
            x2 = x[3 * pid + 2];
        }
        x0 = fminf(fmaxf(x0, -1.f), 1.f);
        x1 = fminf(fmaxf(x1, -1.f), 1.f);
        x2 = fminf(fmaxf(x2, -1.f), 1.f);
        const float X0 = x0 + 1.f, X1 = x1 + 1.f, X2 = x2 + 1.f;

        // 2-stage software pipeline over levels
        float4 eb[2][4];
        unsigned mb[2];
        float w0b[2], w1b[2], w2b[2];

        load_level(emb, 0, inv.v[0], X0, X1, X2,
                   eb[0], mb[0], w0b[0], w1b[0], w2b[0]);

#pragma unroll
        for (int lvl = 0; lvl < NLEV; ++lvl) {
            const int cur = lvl & 1;
            if (lvl + 1 < NLEV)
                load_level(emb, lvl + 1, inv.v[lvl + 1], X0, X1, X2,
                           eb[cur ^ 1], mb[cur ^ 1],
                           w0b[cur ^ 1], w1b[cur ^ 1], w2b[cur ^ 1]);
            float a0, a1;
            consume_level(eb[cur], mb[cur], w0b[cur], w1b[cur], w2b[cur], a0, a1);
            stage[tid * 33 + 2 * lvl + 0] = a0;
            stage[tid * 33 + 2 * lvl + 1] = a1;
        }

        __syncthreads();

        // coalesced streaming write-out (don't pollute L2: tables live there)
        const long long obase = (long long)base_pt * 32;
        const long long rem = (long long)n * 32 - obase;
        const int lim = rem > (long long)(TPB * 32) ? (TPB * 32) : (int)rem;
        for (int i = tid; i < lim; i += TPB) {
            __stcs(&out[obase + i], stage[(i >> 5) * 33 + (i & 31)]);
        }

        __syncthreads();   // stage reused next iteration
    }
}

extern "C" void kernel_launch(void* const* d_in, const int* in_sizes, int n_in,
                              void* d_out, int out_size)
{
    const float* x   = (const float*)d_in[0];
    const float* emb = (const float*)d_in[1];
    float* out = (float*)d_out;

    const int n = in_sizes[0] / 3;

    InvArr inv;
    {
        const double b = exp((log(512.0) - log(16.0)) / 15.0);
        for (int i = 0; i < NLEV; ++i)
            inv.v[i] = (float)(floor(16.0 * pow(b, (double)i)) * 0.5);
    }

    int sm_count = 148;
    cudaDeviceGetAttribute(&sm_count, cudaDevAttrMultiProcessorCount, 0);

    int grid = sm_count * 4;                 // 4 resident blocks per SM
    const int max_grid = (n + TPB - 1) / TPB;
    if (grid > max_grid) grid = max_grid;

    ingp_hash_kernel<<<grid, TPB>>>(x, emb, out, n, inv);
}

// round 9
// speedup vs baseline: 1.0618x; 1.0618x over previous
#include <cuda_runtime.h>
#include <math.h>

#define NLEV 16
#define TABLE_SIZE (1u << 19)
#define TMASK (TABLE_SIZE - 1u)
#define PRIME_Y 2654435761u
#define PRIME_Z 805459861u
#define TPB 256

struct InvArr { float v[NLEV]; };   // res/2 per level

// ---- load phase: weights + all gathers for one level -----------------------
// PRIME_X == 1: for even bl.x the corners (bl.x, bl.x+1) hash to h and h^1 ->
// one aligned float4 load (halves wavefronts). Odd bl.x: 8 float2 loads.
__device__ __forceinline__ void load_level(
    const float* __restrict__ emb, int lvl, float invg,
    float X0, float X1, float X2,
    float4 e[4], unsigned& meta, float& w0, float& w1, float& w2)
{
    const float t0 = X0 * invg, t1 = X1 * invg, t2 = X2 * invg;
    const float f0 = floorf(t0), f1 = floorf(t1), f2 = floorf(t2);
    w0 = t0 - f0; w1 = t1 - f1; w2 = t2 - f2;

    const unsigned hx = (unsigned)(int)f0;
    const unsigned hy = (unsigned)(int)f1 * PRIME_Y;
    const unsigned hz = (unsigned)(int)f2 * PRIME_Z;
    const unsigned r0 = hy ^ hz;
    const unsigned r1 = hy ^ (hz + PRIME_Z);
    const unsigned r2 = (hy + PRIME_Y) ^ hz;
    const unsigned r3 = (hy + PRIME_Y) ^ (hz + PRIME_Z);
    const unsigned h0 = (hx ^ r0) & TMASK, h1 = (hx ^ r1) & TMASK;
    const unsigned h2 = (hx ^ r2) & TMASK, h3 = (hx ^ r3) & TMASK;

    const float2* tab2 = (const float2*)emb + (size_t)lvl * TABLE_SIZE;
    const float4* tab4 = (const float4*)tab2;

    if ((hx & 1u) == 0u) {
        e[0] = __ldg(&tab4[h0 >> 1]);
        e[1] = __ldg(&tab4[h1 >> 1]);
        e[2] = __ldg(&tab4[h2 >> 1]);
        e[3] = __ldg(&tab4[h3 >> 1]);
        // odd h: corner bl lives in .zw, bl+1 in .xy -> swap weights at consume
        meta = (h0 & 1u) | ((h1 & 1u) << 1) | ((h2 & 1u) << 2) | ((h3 & 1u) << 3);
    } else {
        const unsigned hx1 = hx + 1u;
        const unsigned g0 = (hx1 ^ r0) & TMASK, g1 = (hx1 ^ r1) & TMASK;
        const unsigned g2 = (hx1 ^ r2) & TMASK, g3 = (hx1 ^ r3) & TMASK;
        float2 a0 = __ldg(&tab2[h0]), b0 = __ldg(&tab2[g0]);
        float2 a1 = __ldg(&tab2[h1]), b1 = __ldg(&tab2[g1]);
        float2 a2 = __ldg(&tab2[h2]), b2 = __ldg(&tab2[g2]);
        float2 a3 = __ldg(&tab2[h3]), b3 = __ldg(&tab2[g3]);
        e[0] = make_float4(a0.x, a0.y, b0.x, b0.y);
        e[1] = make_float4(a1.x, a1.y, b1.x, b1.y);
        e[2] = make_float4(a2.x, a2.y, b2.x, b2.y);
        e[3] = make_float4(a3.x, a3.y, b3.x, b3.y);
        meta = 0u;
    }
}

// ---- consume: trilinear accumulate (swap WEIGHTS, not values: 2 SEL/corner)
__device__ __forceinline__ void consume_level(
    const float4 e[4], unsigned meta,
    float w0, float w1, float w2, float& a0, float& a1)
{
    const float u0 = 1.f - w0, u1 = 1.f - w1, u2 = 1.f - w2;
    float c[4];
    c[0] = u1 * u2; c[1] = u1 * w2; c[2] = w1 * u2; c[3] = w1 * w2;
    a0 = 0.f; a1 = 0.f;
#pragma unroll
    for (int k = 0; k < 4; ++k) {
        const bool sw = (meta >> k) & 1u;
        const float wA = c[k] * (sw ? w0 : u0);   // weight for slots .xy
        const float wB = c[k] * (sw ? u0 : w0);   // weight for slots .zw
        a0 = fmaf(wA, e[k].x, fmaf(wB, e[k].z, a0));
        a1 = fmaf(wA, e[k].y, fmaf(wB, e[k].w, a1));
    }
}

__global__ void __launch_bounds__(TPB, 3)
ingp_hash_kernel(const float* __restrict__ x,
                 const float* __restrict__ emb,
                 float* __restrict__ out,
                 int n, InvArr inv)
{
    // pitch-33 rows: conflict-free staged writes AND coalesced readback
    __shared__ float stage[TPB * 33];

    const int tid = threadIdx.x;
    const int pid = blockIdx.x * TPB + tid;

    float x0 = 0.f, x1 = 0.f, x2 = 0.f;
    if (pid < n) {
        x0 = x[3 * pid + 0];
        x1 = x[3 * pid + 1];
        x2 = x[3 * pid + 2];
    }
    x0 = fminf(fmaxf(x0, -1.f), 1.f);
    x1 = fminf(fmaxf(x1, -1.f), 1.f);
    x2 = fminf(fmaxf(x2, -1.f), 1.f);
    const float X0 = x0 + 1.f, X1 = x1 + 1.f, X2 = x2 + 1.f;

    // 3-stage software pipeline: levels l+1 and l+2 are in flight while
    // level l is consumed (~12 outstanding gathers/warp -> covers L2 latency)
    float4 eb[3][4];
    unsigned mb[3];
    float w0b[3], w1b[3], w2b[3];

    load_level(emb, 0, inv.v[0], X0, X1, X2, eb[0], mb[0], w0b[0], w1b[0], w2b[0]);
    load_level(emb, 1, inv.v[1], X0, X1, X2, eb[1], mb[1], w0b[1], w1b[1], w2b[1]);

#pragma unroll
    for (int lvl = 0; lvl < NLEV; ++lvl) {
        const int cur = lvl % 3;
        if (lvl + 2 < NLEV) {
            const int nxt = (lvl + 2) % 3;
            load_level(emb, lvl + 2, inv.v[lvl + 2], X0, X1, X2,
                       eb[nxt], mb[nxt], w0b[nxt], w1b[nxt], w2b[nxt]);
        }
        float a0, a1;
        consume_level(eb[cur], mb[cur], w0b[cur], w1b[cur], w2b[cur], a0, a1);
        stage[tid * 33 + 2 * lvl + 0] = a0;
        stage[tid * 33 + 2 * lvl + 1] = a1;
    }

    __syncthreads();

    // coalesced streaming write-out (don't pollute L2: tables live there)
    const long long base = (long long)blockIdx.x * (TPB * 32);
    const long long rem = (long long)n * 32 - base;
    const int lim = rem > (long long)(TPB * 32) ? (TPB * 32) : (int)rem;
    for (int i = tid; i < lim; i += TPB) {
        __stcs(&out[base + i], stage[(i >> 5) * 33 + (i & 31)]);
    }
}

extern "C" void kernel_launch(void* const* d_in, const int* in_sizes, int n_in,
                              void* d_out, int out_size)
{
    const float* x   = (const float*)d_in[0];
    const float* emb = (const float*)d_in[1];
    float* out = (float*)d_out;

    const int n = in_sizes[0] / 3;

    InvArr inv;
    {
        const double b = exp((log(512.0) - log(16.0)) / 15.0);
        for (int i = 0; i < NLEV; ++i)
            inv.v[i] = (float)(floor(16.0 * pow(b, (double)i)) * 0.5);
    }

    const int grid = (n + TPB - 1) / TPB;
    ingp_hash_kernel<<<grid, TPB>>>(x, emb, out, n, inv);
}